// round 1
// baseline (speedup 1.0000x reference)
#include <cuda_runtime.h>
#include <math.h>

// Problem constants
#define NPTS 131072          // B*N = 1024*128
#define NEDG 524288          // NPTS * K(=4)

// Scratch (device globals; no allocation allowed)
__device__ float g_X453[(size_t)NPTS * 456];   // concat buffer: [feat(5) | out1(64) | out2(128) | out3(256)] pad->456
__device__ float g_PQ[(size_t)NPTS * 384];     // P|Q buffer (max 2H=384); reused as H2 (226 cols)
__device__ float g_H1[(size_t)NPTS * 453];     // head intermediate
__device__ int   g_idx[NPTS * 4];              // knn neighbor global row indices
__device__ float g_Wpq[128 * 384];             // prepped [w1a | w1b] per layer (max 128 x 384)

__device__ __forceinline__ float eluf(float x) { return x > 0.f ? x : expm1f(x); }

// ---------------- elementwise helpers ----------------
__global__ void copy_features_k(const float* __restrict__ f, float* __restrict__ X) {
    int e = blockIdx.x * blockDim.x + threadIdx.x;
    if (e < NPTS * 5) {
        int r = e / 5, c = e % 5;
        X[(size_t)r * 456 + c] = f[e];
    }
}

// w1: [2C, H] row-major.  out[c][0:H] = w1[c] - w1[C+c];  out[c][H:2H] = w1[C+c]
__global__ void prep_wpq_k(const float* __restrict__ w1, float* __restrict__ out, int C, int H) {
    int e = blockIdx.x * blockDim.x + threadIdx.x;
    if (e < C * H) {
        int c = e / H, h = e % H;
        float a = w1[c * H + h];
        float b = w1[(C + c) * H + h];
        out[c * 2 * H + h]     = a - b;
        out[c * 2 * H + H + h] = b;
    }
}

// ---------------- KNN (k=4, N=128 per batch, block = one batch) ----------------
// Matches reference formula d = |xi|^2 + |xj|^2 - 2*dot(xi,xj); self excluded; ties keep lower index.
template<int C, int CP>   // CP = padded column count (multiple of 4)
__global__ void __launch_bounds__(128) knn_k(const float* __restrict__ x, int ld, int cofs,
                                             int* __restrict__ idxout) {
    constexpr int PAD = CP + 4;                  // conflict-mitigating row pad (keeps 16B alignment)
    __shared__ __align__(16) float sx[32][PAD];
    __shared__ float sn[128];
    int b = blockIdx.x;
    int tid = threadIdx.x;                       // = point index i within batch
    const float* xb = x + (size_t)b * 128 * ld + cofs;
    float4 xi[CP / 4];

    // pass 0: stage tiles, extract own row into registers
    for (int t = 0; t < 4; t++) {
        for (int e = tid; e < 32 * CP; e += 128) {
            int r = e / CP, c = e % CP;
            sx[r][c] = (c < C) ? xb[(size_t)(t * 32 + r) * ld + c] : 0.f;
        }
        __syncthreads();
        if ((tid >> 5) == t) {
            int r = tid & 31;
            #pragma unroll
            for (int c4 = 0; c4 < CP / 4; c4++)
                xi[c4] = *(const float4*)&sx[r][4 * c4];
        }
        __syncthreads();
    }
    float ni = 0.f;
    #pragma unroll
    for (int c4 = 0; c4 < CP / 4; c4++)
        ni += xi[c4].x * xi[c4].x + xi[c4].y * xi[c4].y + xi[c4].z * xi[c4].z + xi[c4].w * xi[c4].w;
    sn[tid] = ni;
    __syncthreads();

    float bd0 = 1e30f, bd1 = 1e30f, bd2 = 1e30f, bd3 = 1e30f;
    int   bi0 = 0,     bi1 = 0,     bi2 = 0,     bi3 = 0;

    for (int t = 0; t < 4; t++) {
        for (int e = tid; e < 32 * CP; e += 128) {
            int r = e / CP, c = e % CP;
            sx[r][c] = (c < C) ? xb[(size_t)(t * 32 + r) * ld + c] : 0.f;
        }
        __syncthreads();
        for (int jl = 0; jl < 32; jl++) {
            int j = t * 32 + jl;
            float dot = 0.f;
            #pragma unroll
            for (int c4 = 0; c4 < CP / 4; c4++) {
                float4 xj = *(const float4*)&sx[jl][4 * c4];
                dot += xi[c4].x * xj.x + xi[c4].y * xj.y + xi[c4].z * xj.z + xi[c4].w * xj.w;
            }
            float d = ni + sn[j] - 2.f * dot;
            if (j == tid) d = 1e30f;             // exclude self
            if (d < bd3) {
                if (d < bd2) {
                    bd3 = bd2; bi3 = bi2;
                    if (d < bd1) {
                        bd2 = bd1; bi2 = bi1;
                        if (d < bd0) { bd1 = bd0; bi1 = bi0; bd0 = d; bi0 = j; }
                        else         { bd1 = d; bi1 = j; }
                    } else { bd2 = d; bi2 = j; }
                } else { bd3 = d; bi3 = j; }
            }
        }
        __syncthreads();
    }
    int base = (b * 128 + tid) * 4;
    int gb = b * 128;
    idxout[base + 0] = gb + bi0;
    idxout[base + 1] = gb + bi1;
    idxout[base + 2] = gb + bi2;
    idxout[base + 3] = gb + bi3;
}

// ---------------- Generic fp32 tiled GEMM ----------------
// C[M,N] = epilogue(A[M,K] @ W[K,N])
// GATHER: A-row m = elu(PQ[m>>2][k] + PQ[eidx[m]][qofs+k] + b1[k])
// ACT:    elu(acc + bias)
// RED:    mean over 4 consecutive M-rows (thread owns exactly one edge-group)
// Block: 64x64 tile, BK=16, 128 threads, each thread 4(M, consecutive) x 8(N).
template<int GATHER, int ACT, int RED>
__global__ void __launch_bounds__(128) gemm_k(
    const float* __restrict__ A, int lda,
    const float* __restrict__ PQ, int ldpq, int qofs,
    const float* __restrict__ b1, const int* __restrict__ eidx,
    const float* __restrict__ W, int ldw,
    const float* __restrict__ bias,
    float* __restrict__ Co, int ldc, int cofs,
    int K, int N)
{
    __shared__ __align__(16) float As[16][68];   // [k][m], padded
    __shared__ __align__(16) float Ws[16][64];   // [k][n]
    int tid = threadIdx.x;
    int tm = tid & 15, tn = tid >> 4;
    int row0 = blockIdx.x * 64;
    int n0 = blockIdx.y * 64;
    float acc[4][8];
    #pragma unroll
    for (int r = 0; r < 4; r++)
        #pragma unroll
        for (int c = 0; c < 8; c++) acc[r][c] = 0.f;

    for (int k0 = 0; k0 < K; k0 += 16) {
        #pragma unroll
        for (int it = 0; it < 8; it++) {
            int e = tid + it * 128;
            int m = e >> 4, k = e & 15;
            int kg = k0 + k;
            float v = 0.f;
            if (kg < K) {
                if (GATHER) {
                    int mg = row0 + m;
                    int ip = mg >> 2;
                    int jp = eidx[mg];
                    v = eluf(PQ[(size_t)ip * ldpq + kg] + PQ[(size_t)jp * ldpq + qofs + kg] + b1[kg]);
                } else {
                    v = A[(size_t)(row0 + m) * lda + kg];
                }
            }
            As[k][m] = v;
        }
        #pragma unroll
        for (int it = 0; it < 8; it++) {
            int e = tid + it * 128;
            int kr = e >> 6, c = e & 63;
            int kg = k0 + kr, ng = n0 + c;
            Ws[kr][c] = (kg < K && ng < N) ? W[(size_t)kg * ldw + ng] : 0.f;
        }
        __syncthreads();
        #pragma unroll
        for (int kk = 0; kk < 16; kk++) {
            float4 a  = *(const float4*)&As[kk][4 * tm];
            float4 w0 = *(const float4*)&Ws[kk][8 * tn];
            float4 w1 = *(const float4*)&Ws[kk][8 * tn + 4];
            float av[4] = {a.x, a.y, a.z, a.w};
            float wv[8] = {w0.x, w0.y, w0.z, w0.w, w1.x, w1.y, w1.z, w1.w};
            #pragma unroll
            for (int r = 0; r < 4; r++)
                #pragma unroll
                for (int c = 0; c < 8; c++)
                    acc[r][c] += av[r] * wv[c];
        }
        __syncthreads();
    }

    float bv[8];
    #pragma unroll
    for (int c = 0; c < 8; c++) {
        int ng = n0 + 8 * tn + c;
        bv[c] = (bias != nullptr && ng < N) ? bias[ng] : 0.f;
    }
    if (RED) {
        int p = (row0 >> 2) + tm;                // point index
        #pragma unroll
        for (int c = 0; c < 8; c++) {
            int ng = n0 + 8 * tn + c;
            if (ng < N) {
                float s = 0.f;
                #pragma unroll
                for (int r = 0; r < 4; r++) {
                    float v = acc[r][c] + bv[c];
                    if (ACT) v = eluf(v);
                    s += v;
                }
                Co[(size_t)p * ldc + cofs + ng] = 0.25f * s;
            }
        }
    } else {
        #pragma unroll
        for (int r = 0; r < 4; r++) {
            int mg = row0 + 4 * tm + r;
            #pragma unroll
            for (int c = 0; c < 8; c++) {
                int ng = n0 + 8 * tn + c;
                if (ng < N) {
                    float v = acc[r][c] + bv[c];
                    if (ACT) v = eluf(v);
                    Co[(size_t)mg * ldc + cofs + ng] = v;
                }
            }
        }
    }
}

// ---------------- final tiny GEMM: out = H2[131072,226] @ w3[226,2] + b3 ----------------
__global__ void head3_k(const float* __restrict__ H2, const float* __restrict__ w,
                        const float* __restrict__ b, float* __restrict__ out) {
    int gtid = blockIdx.x * blockDim.x + threadIdx.x;
    int warp = gtid >> 5;
    int lane = threadIdx.x & 31;
    if (warp >= NPTS) return;
    const float* hr = H2 + (size_t)warp * 226;
    float a0 = 0.f, a1 = 0.f;
    for (int c = lane; c < 226; c += 32) {
        float h = hr[c];
        a0 += h * w[2 * c];
        a1 += h * w[2 * c + 1];
    }
    #pragma unroll
    for (int o = 16; o; o >>= 1) {
        a0 += __shfl_xor_sync(0xffffffffu, a0, o);
        a1 += __shfl_xor_sync(0xffffffffu, a1, o);
    }
    if (lane == 0) {
        out[2 * warp + 0] = a0 + b[0];
        out[2 * warp + 1] = a1 + b[1];
    }
}

extern "C" void kernel_launch(void* const* d_in, const int* in_sizes, int n_in,
                              void* d_out, int out_size) {
    const float* coords   = (const float*)d_in[0];
    const float* features = (const float*)d_in[1];
    const float* c1w1 = (const float*)d_in[2];
    const float* c1b1 = (const float*)d_in[3];
    const float* c1w2 = (const float*)d_in[4];
    const float* c1b2 = (const float*)d_in[5];
    const float* c2w1 = (const float*)d_in[6];
    const float* c2b1 = (const float*)d_in[7];
    const float* c2w2 = (const float*)d_in[8];
    const float* c2b2 = (const float*)d_in[9];
    const float* c3w1 = (const float*)d_in[10];
    const float* c3b1 = (const float*)d_in[11];
    const float* c3w2 = (const float*)d_in[12];
    const float* c3b2 = (const float*)d_in[13];
    const float* ow1  = (const float*)d_in[14];
    const float* ob1  = (const float*)d_in[15];
    const float* ow2  = (const float*)d_in[16];
    const float* ob2  = (const float*)d_in[17];
    const float* ow3  = (const float*)d_in[18];
    const float* ob3  = (const float*)d_in[19];

    float *pX, *pPQ, *pH1, *pW; int* pidx;
    cudaGetSymbolAddress((void**)&pX,  g_X453);
    cudaGetSymbolAddress((void**)&pPQ, g_PQ);
    cudaGetSymbolAddress((void**)&pH1, g_H1);
    cudaGetSymbolAddress((void**)&pW,  g_Wpq);
    cudaGetSymbolAddress((void**)&pidx, g_idx);

    // features -> X453[:, 0:5]
    copy_features_k<<<(NPTS * 5 + 255) / 256, 256>>>(features, pX);

    // ===== EdgeConv 1 (C=5, H=32, O=64) =====
    knn_k<2, 4><<<1024, 128>>>(coords, 2, 0, pidx);
    prep_wpq_k<<<1, 256>>>(c1w1, pW, 5, 32);
    gemm_k<0, 0, 0><<<dim3(NPTS / 64, 1), 128>>>(pX, 456, nullptr, 0, 0, nullptr, nullptr,
                                                 pW, 64, nullptr, pPQ, 64, 0, 5, 64);
    gemm_k<1, 1, 1><<<dim3(NEDG / 64, 1), 128>>>(nullptr, 0, pPQ, 64, 32, c1b1, pidx,
                                                 c1w2, 64, c1b2, pX, 456, 5, 32, 64);

    // ===== EdgeConv 2 (C=64, H=96, O=128) =====
    knn_k<64, 64><<<1024, 128>>>(pX, 456, 5, pidx);
    prep_wpq_k<<<(64 * 96 + 255) / 256, 256>>>(c2w1, pW, 64, 96);
    gemm_k<0, 0, 0><<<dim3(NPTS / 64, 3), 128>>>(pX + 5, 456, nullptr, 0, 0, nullptr, nullptr,
                                                 pW, 192, nullptr, pPQ, 192, 0, 64, 192);
    gemm_k<1, 1, 1><<<dim3(NEDG / 64, 2), 128>>>(nullptr, 0, pPQ, 192, 96, c2b1, pidx,
                                                 c2w2, 128, c2b2, pX, 456, 69, 96, 128);

    // ===== EdgeConv 3 (C=128, H=192, O=256) =====
    knn_k<128, 128><<<1024, 128>>>(pX, 456, 69, pidx);
    prep_wpq_k<<<(128 * 192 + 255) / 256, 256>>>(c3w1, pW, 128, 192);
    gemm_k<0, 0, 0><<<dim3(NPTS / 64, 6), 128>>>(pX + 69, 456, nullptr, 0, 0, nullptr, nullptr,
                                                 pW, 384, nullptr, pPQ, 384, 0, 128, 384);
    gemm_k<1, 1, 1><<<dim3(NEDG / 64, 4), 128>>>(nullptr, 0, pPQ, 384, 192, c3b1, pidx,
                                                 c3w2, 256, c3b2, pX, 456, 197, 192, 256);

    // ===== Head =====
    gemm_k<0, 1, 0><<<dim3(NPTS / 64, 8), 128>>>(pX, 456, nullptr, 0, 0, nullptr, nullptr,
                                                 ow1, 453, ob1, pH1, 453, 0, 453, 453);
    gemm_k<0, 1, 0><<<dim3(NPTS / 64, 4), 128>>>(pH1, 453, nullptr, 0, 0, nullptr, nullptr,
                                                 ow2, 226, ob2, pPQ, 226, 0, 453, 226);
    head3_k<<<(NPTS * 32) / 256, 256>>>(pPQ, ow3, ob3, (float*)d_out);
}

// round 4
// speedup vs baseline: 1.7759x; 1.7759x over previous
#include <cuda_runtime.h>
#include <cstdint>
#include <math.h>

// ============================ problem constants ============================
#define NPTS 131072          // B*N = 1024*128
#define NEDG 524288          // NPTS * K(=4)

// Concat buffer layout (all segment starts 16B-aligned; pads never written => 0)
#define F_OFS  0             // features: cols 0..4   (pads 5..7)
#define O1_OFS 8             // out1:     cols 8..71
#define O2_OFS 72            // out2:     cols 72..199
#define O3_OFS 200           // out3:     cols 200..455
#define XLD    456           // 456*4 bytes = 1824 = 16*114 -> rows aligned

// ============================ device scratch ===============================
__device__ float g_X453[(size_t)NPTS * XLD];   // padded concat buffer
__device__ float g_PQ[(size_t)NPTS * 384];     // P|Q buffer (max 384 cols); reused as H2 (ld 228)
__device__ float g_H1[(size_t)NPTS * 456];     // head intermediate (ld 456, cols 453..455 stay 0)
__device__ int   g_idx[NPTS * 4];              // knn neighbor global row indices
__device__ float g_Wt[512 * 480];              // transposed weights Wt[n][kpad]

__device__ __forceinline__ float eluf(float x) { return x > 0.f ? x : expm1f(x); }

// ============================ small helpers ================================
__device__ __forceinline__ uint32_t smem_u32(const void* p) {
    uint32_t a;
    asm("{ .reg .u64 t; cvta.to.shared.u64 t, %1; cvt.u32.u64 %0, t; }" : "=r"(a) : "l"(p));
    return a;
}
__device__ __forceinline__ void cp_async16(uint32_t dst, const float* src) {
    uint64_t g = (uint64_t)__cvta_generic_to_global(src);
    asm volatile("cp.async.ca.shared.global [%0], [%1], 16;" :: "r"(dst), "l"(g) : "memory");
}
__device__ __forceinline__ void sp_tf32(float a, uint32_t& h, uint32_t& l) {
    uint32_t hu;
    asm("cvt.rna.tf32.f32 %0, %1;" : "=r"(hu) : "f"(a));
    float lf = a - __uint_as_float(hu);
    uint32_t lu;
    asm("cvt.rna.tf32.f32 %0, %1;" : "=r"(lu) : "f"(lf));
    h = hu; l = lu;
}
__device__ __forceinline__ void mma8(float* c, const uint32_t* a, const uint32_t* b) {
    asm volatile("mma.sync.aligned.m16n8k8.row.col.f32.tf32.tf32.f32 "
                 "{%0,%1,%2,%3}, {%4,%5,%6,%7}, {%8,%9}, {%0,%1,%2,%3};"
                 : "+f"(c[0]), "+f"(c[1]), "+f"(c[2]), "+f"(c[3])
                 : "r"(a[0]), "r"(a[1]), "r"(a[2]), "r"(a[3]), "r"(b[0]), "r"(b[1]));
}

// ============================ elementwise helpers ==========================
__global__ void copy_features_k(const float* __restrict__ f, float* __restrict__ X) {
    int e = blockIdx.x * blockDim.x + threadIdx.x;
    if (e < NPTS * 5) {
        int r = e / 5, c = e % 5;
        X[(size_t)r * XLD + c] = f[e];
    }
}
// w1[2C,H] -> Wt rows: n<H: w1_top - w1_bot ; n>=H: w1_bot   (cols k padded to Kpad)
__global__ void prep_pq_k(const float* __restrict__ w1, float* __restrict__ wt, int C, int H, int Kpad) {
    int e = blockIdx.x * blockDim.x + threadIdx.x;
    if (e >= 2 * H * Kpad) return;
    int n = e / Kpad, k = e % Kpad;
    float v = 0.f;
    if (k < C) v = (n < H) ? (w1[k * H + n] - w1[(C + k) * H + n]) : w1[(C + k) * H + (n - H)];
    wt[(size_t)n * Kpad + k] = v;
}
// w[K,N] -> Wt[n][kpad]
__global__ void prep_wt_k(const float* __restrict__ w, float* __restrict__ wt, int K, int N, int Kpad) {
    int e = blockIdx.x * blockDim.x + threadIdx.x;
    if (e >= N * Kpad) return;
    int n = e / Kpad, k = e % Kpad;
    wt[(size_t)n * Kpad + k] = (k < K) ? w[(size_t)k * N + n] : 0.f;
}
// head-1 weights: w[453,N] against PADDED concat k-layout (456 cols), Kpad=480.
// padded col kp -> original k: kp<5 -> kp ; 8<=kp<456 -> kp-3 ; else zero row.
__global__ void prep_head_k(const float* __restrict__ w, float* __restrict__ wt, int N, int Kpad) {
    int e = blockIdx.x * blockDim.x + threadIdx.x;
    if (e >= N * Kpad) return;
    int n = e / Kpad, kp = e % Kpad;
    float v = 0.f;
    if (kp < 5)                 v = w[(size_t)kp * N + n];
    else if (kp >= 8 && kp < 456) v = w[(size_t)(kp - 3) * N + n];
    wt[(size_t)n * Kpad + kp] = v;
}

// ============================ KNN (k=4, per-batch block) ===================
template<int C, int CP>
__global__ void __launch_bounds__(128) knn_k(const float* __restrict__ x, int ld, int cofs,
                                             int* __restrict__ idxout) {
    constexpr int PAD = CP + 4;
    __shared__ __align__(16) float sx[32][PAD];
    __shared__ float sn[128];
    int b = blockIdx.x;
    int tid = threadIdx.x;
    const float* xb = x + (size_t)b * 128 * ld + cofs;
    float4 xi[CP / 4];

    for (int t = 0; t < 4; t++) {
        for (int e = tid; e < 32 * CP; e += 128) {
            int r = e / CP, c = e % CP;
            sx[r][c] = (c < C) ? xb[(size_t)(t * 32 + r) * ld + c] : 0.f;
        }
        __syncthreads();
        if ((tid >> 5) == t) {
            int r = tid & 31;
            #pragma unroll
            for (int c4 = 0; c4 < CP / 4; c4++) xi[c4] = *(const float4*)&sx[r][4 * c4];
        }
        __syncthreads();
    }
    float ni = 0.f;
    #pragma unroll
    for (int c4 = 0; c4 < CP / 4; c4++)
        ni += xi[c4].x * xi[c4].x + xi[c4].y * xi[c4].y + xi[c4].z * xi[c4].z + xi[c4].w * xi[c4].w;
    sn[tid] = ni;
    __syncthreads();

    float bd0 = 1e30f, bd1 = 1e30f, bd2 = 1e30f, bd3 = 1e30f;
    int   bi0 = 0,     bi1 = 0,     bi2 = 0,     bi3 = 0;

    for (int t = 0; t < 4; t++) {
        for (int e = tid; e < 32 * CP; e += 128) {
            int r = e / CP, c = e % CP;
            sx[r][c] = (c < C) ? xb[(size_t)(t * 32 + r) * ld + c] : 0.f;
        }
        __syncthreads();
        for (int jl = 0; jl < 32; jl++) {
            int j = t * 32 + jl;
            float dot = 0.f;
            #pragma unroll
            for (int c4 = 0; c4 < CP / 4; c4++) {
                float4 xj = *(const float4*)&sx[jl][4 * c4];
                dot += xi[c4].x * xj.x + xi[c4].y * xj.y + xi[c4].z * xj.z + xi[c4].w * xj.w;
            }
            float d = ni + sn[j] - 2.f * dot;
            if (j == tid) d = 1e30f;
            if (d < bd3) {
                if (d < bd2) {
                    bd3 = bd2; bi3 = bi2;
                    if (d < bd1) {
                        bd2 = bd1; bi2 = bi1;
                        if (d < bd0) { bd1 = bd0; bi1 = bi0; bd0 = d; bi0 = j; }
                        else         { bd1 = d; bi1 = j; }
                    } else { bd2 = d; bi2 = j; }
                } else { bd3 = d; bi3 = j; }
            }
        }
        __syncthreads();
    }
    int base = (b * 128 + tid) * 4;
    int gb = b * 128;
    idxout[base + 0] = gb + bi0;
    idxout[base + 1] = gb + bi1;
    idxout[base + 2] = gb + bi2;
    idxout[base + 3] = gb + bi3;
}

// ============================ mma.sync tf32 GEMM ===========================
// CTA tile 128(M) x 64(N) x 32(K); 256 thr = 8 warps (4m x 2n); warp 32x32.
// 3xTF32 split in registers. Double-buffered cp.async stages.
// GATHER: A-row m = elu(P[m>>2][k] + Q[eidx[m]][qofs+k] + b1[k])
// ACT: elu(acc+bias). RED: mean over 4 consecutive M rows -> point row.
#define AP 36
#define AFLTS (128 * AP)
#define BFLTS (64 * AP)
template<int GATHER, int ACT, int RED>
__global__ void __launch_bounds__(256) mmagemm_k(
    const float* __restrict__ A, int lda, int Kval,
    const float* __restrict__ PQ, int ldpq, int qofs,
    const float* __restrict__ b1, const int* __restrict__ eidx,
    const float* __restrict__ Wt, int Kpad,
    const float* __restrict__ bias,
    float* __restrict__ Co, int ldc, int cofs, int Nfull)
{
    extern __shared__ float sm[];
    const uint32_t sbase = smem_u32(sm);
    const int tid = threadIdx.x;
    const int wid = tid >> 5, lane = tid & 31;
    const int g = lane >> 2, q = lane & 3;
    const int warp_m = wid >> 1, warp_n = wid & 1;
    const int m0 = blockIdx.x * 128;
    const int n0 = blockIdx.y * 64;
    const int iters = Kpad >> 5;
    const int aoff[2] = {0, AFLTS};
    const int boff[2] = {2 * AFLTS, 2 * AFLTS + BFLTS};

    // gather per-thread constants
    const float *Pp = nullptr, *Qp = nullptr;
    int lr = tid >> 1, lh = (tid & 1) << 4;
    if (GATHER) {
        int mg = m0 + lr;
        Pp = PQ + (size_t)(mg >> 2) * ldpq;
        Qp = PQ + (size_t)eidx[mg] * ldpq + qofs;
    }

    float acc[2][4][4];
    #pragma unroll
    for (int mt = 0; mt < 2; mt++)
        #pragma unroll
        for (int nt = 0; nt < 4; nt++)
            #pragma unroll
            for (int i = 0; i < 4; i++) acc[mt][nt][i] = 0.f;

    // ---- tile loader ----
    auto load_tile = [&](int s, int it) {
        const int k0 = it << 5;
        if (GATHER) {
            const float* Pr = Pp + k0;
            const float* Qr = Qp + k0;
            const float* Br = b1 + k0;
            #pragma unroll
            for (int qq = 0; qq < 4; qq++) {
                int kk = lh + (qq << 2);
                float4 pv = *(const float4*)(Pr + kk);
                float4 qv = *(const float4*)(Qr + kk);
                float4 bv = *(const float4*)(Br + kk);
                float4 v;
                v.x = eluf(pv.x + qv.x + bv.x);
                v.y = eluf(pv.y + qv.y + bv.y);
                v.z = eluf(pv.z + qv.z + bv.z);
                v.w = eluf(pv.w + qv.w + bv.w);
                *(float4*)&sm[aoff[s] + lr * AP + kk] = v;
            }
        } else {
            #pragma unroll
            for (int i = 0; i < 4; i++) {
                int c = tid + (i << 8);
                int m = c >> 3, kc = (c & 7) << 2, gk = k0 + kc;
                int off = aoff[s] + m * AP + kc;
                const float* src = A + (size_t)(m0 + m) * lda + gk;
                if (gk + 3 < Kval) {
                    cp_async16(sbase + off * 4, src);
                } else {
                    float4 v = make_float4(0.f, 0.f, 0.f, 0.f);
                    if (gk + 0 < Kval) v.x = src[0];
                    if (gk + 1 < Kval) v.y = src[1];
                    if (gk + 2 < Kval) v.z = src[2];
                    *(float4*)&sm[off] = v;
                }
            }
        }
        #pragma unroll
        for (int i = 0; i < 2; i++) {
            int c = tid + (i << 8);
            int n = c >> 3, kc = (c & 7) << 2, gn = n0 + n, gk = k0 + kc;
            int off = boff[s] + n * AP + kc;
            if (gn < Nfull) cp_async16(sbase + off * 4, Wt + (size_t)gn * Kpad + gk);
            else            *(float4*)&sm[off] = make_float4(0.f, 0.f, 0.f, 0.f);
        }
        asm volatile("cp.async.commit_group;" ::: "memory");
    };

    load_tile(0, 0);
    for (int it = 0; it < iters; it++) {
        if (it + 1 < iters) {
            load_tile((it + 1) & 1, it + 1);
            asm volatile("cp.async.wait_group 1;" ::: "memory");
        } else {
            asm volatile("cp.async.wait_group 0;" ::: "memory");
        }
        __syncthreads();
        const int s = it & 1;
        const int abase = aoff[s] + (warp_m * 32 + g) * AP;
        const int bbase = boff[s] + (warp_n * 32 + g) * AP;
        #pragma unroll
        for (int ks = 0; ks < 4; ks++) {
            const int kb = (ks << 3) + q;
            uint32_t ah[2][4], al[2][4];
            #pragma unroll
            for (int mt = 0; mt < 2; mt++) {
                int rb = abase + mt * 16 * AP;
                sp_tf32(sm[rb + kb],              ah[mt][0], al[mt][0]);
                sp_tf32(sm[rb + 8 * AP + kb],     ah[mt][1], al[mt][1]);
                sp_tf32(sm[rb + kb + 4],          ah[mt][2], al[mt][2]);
                sp_tf32(sm[rb + 8 * AP + kb + 4], ah[mt][3], al[mt][3]);
            }
            uint32_t bh[4][2], bl[4][2];
            #pragma unroll
            for (int nt = 0; nt < 4; nt++) {
                int rb = bbase + nt * 8 * AP;
                sp_tf32(sm[rb + kb],     bh[nt][0], bl[nt][0]);
                sp_tf32(sm[rb + kb + 4], bh[nt][1], bl[nt][1]);
            }
            #pragma unroll
            for (int mt = 0; mt < 2; mt++)
                #pragma unroll
                for (int nt = 0; nt < 4; nt++) {
                    mma8(acc[mt][nt], ah[mt], bh[nt]);
                    mma8(acc[mt][nt], al[mt], bh[nt]);
                    mma8(acc[mt][nt], ah[mt], bl[nt]);
                }
        }
        __syncthreads();
    }

    // ---- epilogue ----
    #pragma unroll
    for (int mt = 0; mt < 2; mt++) {
        const int rbase = m0 + warp_m * 32 + mt * 16;
        #pragma unroll
        for (int nt = 0; nt < 4; nt++) {
            const int cl = warp_n * 32 + nt * 8 + 2 * q;
            const int gc = n0 + cl;
            float bb0 = 0.f, bb1 = 0.f;
            if (bias != nullptr) {
                if (gc < Nfull)     bb0 = bias[gc];
                if (gc + 1 < Nfull) bb1 = bias[gc + 1];
            }
            if (!RED) {
                float v0 = acc[mt][nt][0] + bb0, v1 = acc[mt][nt][1] + bb1;
                float v2 = acc[mt][nt][2] + bb0, v3 = acc[mt][nt][3] + bb1;
                if (ACT) { v0 = eluf(v0); v1 = eluf(v1); v2 = eluf(v2); v3 = eluf(v3); }
                float* r0 = Co + (size_t)(rbase + g) * ldc + cofs;
                float* r1 = r0 + (size_t)8 * ldc;
                if (gc < Nfull)     { r0[gc] = v0;     r1[gc] = v2; }
                if (gc + 1 < Nfull) { r0[gc + 1] = v1; r1[gc + 1] = v3; }
            } else {
                #pragma unroll
                for (int half = 0; half < 2; half++) {
                    float v0 = (gc < Nfull)     ? eluf(acc[mt][nt][2 * half + 0] + bb0) : 0.f;
                    float v1 = (gc + 1 < Nfull) ? eluf(acc[mt][nt][2 * half + 1] + bb1) : 0.f;
                    v0 += __shfl_xor_sync(0xffffffffu, v0, 4);
                    v0 += __shfl_xor_sync(0xffffffffu, v0, 8);
                    v1 += __shfl_xor_sync(0xffffffffu, v1, 4);
                    v1 += __shfl_xor_sync(0xffffffffu, v1, 8);
                    if ((lane & 12) == 0) {
                        int p = (rbase + half * 8 + g) >> 2;
                        float* op = Co + (size_t)p * ldc + cofs;
                        if (gc < Nfull)     op[gc] = 0.25f * v0;
                        if (gc + 1 < Nfull) op[gc + 1] = 0.25f * v1;
                    }
                }
            }
        }
    }
}

// ============================ final tiny GEMM ==============================
__global__ void head3_k(const float* __restrict__ H2, const float* __restrict__ w,
                        const float* __restrict__ b, float* __restrict__ out) {
    int gtid = blockIdx.x * blockDim.x + threadIdx.x;
    int warp = gtid >> 5;
    int lane = threadIdx.x & 31;
    if (warp >= NPTS) return;
    const float* hr = H2 + (size_t)warp * 228;
    float a0 = 0.f, a1 = 0.f;
    for (int c = lane; c < 226; c += 32) {
        float h = hr[c];
        a0 += h * w[2 * c];
        a1 += h * w[2 * c + 1];
    }
    #pragma unroll
    for (int o = 16; o; o >>= 1) {
        a0 += __shfl_xor_sync(0xffffffffu, a0, o);
        a1 += __shfl_xor_sync(0xffffffffu, a1, o);
    }
    if (lane == 0) {
        out[2 * warp + 0] = a0 + b[0];
        out[2 * warp + 1] = a1 + b[1];
    }
}

// ============================ launcher =====================================
extern "C" void kernel_launch(void* const* d_in, const int* in_sizes, int n_in,
                              void* d_out, int out_size) {
    const float* coords   = (const float*)d_in[0];
    const float* features = (const float*)d_in[1];
    const float* c1w1 = (const float*)d_in[2];
    const float* c1b1 = (const float*)d_in[3];
    const float* c1w2 = (const float*)d_in[4];
    const float* c1b2 = (const float*)d_in[5];
    const float* c2w1 = (const float*)d_in[6];
    const float* c2b1 = (const float*)d_in[7];
    const float* c2w2 = (const float*)d_in[8];
    const float* c2b2 = (const float*)d_in[9];
    const float* c3w1 = (const float*)d_in[10];
    const float* c3b1 = (const float*)d_in[11];
    const float* c3w2 = (const float*)d_in[12];
    const float* c3b2 = (const float*)d_in[13];
    const float* ow1  = (const float*)d_in[14];
    const float* ob1  = (const float*)d_in[15];
    const float* ow2  = (const float*)d_in[16];
    const float* ob2  = (const float*)d_in[17];
    const float* ow3  = (const float*)d_in[18];
    const float* ob3  = (const float*)d_in[19];

    float *pX, *pPQ, *pH1, *pWt; int* pidx;
    cudaGetSymbolAddress((void**)&pX,  g_X453);
    cudaGetSymbolAddress((void**)&pPQ, g_PQ);
    cudaGetSymbolAddress((void**)&pH1, g_H1);
    cudaGetSymbolAddress((void**)&pWt, g_Wt);
    cudaGetSymbolAddress((void**)&pidx, g_idx);

    const int SMEM = (2 * AFLTS + 2 * BFLTS) * 4;   // 55296 B
    cudaFuncSetAttribute(mmagemm_k<0, 0, 0>, cudaFuncAttributeMaxDynamicSharedMemorySize, SMEM);
    cudaFuncSetAttribute(mmagemm_k<1, 1, 1>, cudaFuncAttributeMaxDynamicSharedMemorySize, SMEM);
    cudaFuncSetAttribute(mmagemm_k<0, 1, 0>, cudaFuncAttributeMaxDynamicSharedMemorySize, SMEM);

    const int MT_P = NPTS / 128;   // 1024
    const int MT_E = NEDG / 128;   // 4096

    copy_features_k<<<(NPTS * 5 + 255) / 256, 256>>>(features, pX);

    // ===== EdgeConv 1 (C=5, H=32, O=64) =====
    knn_k<2, 4><<<1024, 128>>>(coords, 2, 0, pidx);
    prep_pq_k<<<(64 * 32 + 255) / 256, 256>>>(c1w1, pWt, 5, 32, 32);
    mmagemm_k<0, 0, 0><<<dim3(MT_P, 1), 256, SMEM>>>(pX, XLD, 5, nullptr, 0, 0, nullptr, nullptr,
                                                     pWt, 32, nullptr, pPQ, 64, 0, 64);
    prep_wt_k<<<(64 * 32 + 255) / 256, 256>>>(c1w2, pWt, 32, 64, 32);
    mmagemm_k<1, 1, 1><<<dim3(MT_E, 1), 256, SMEM>>>(nullptr, 0, 32, pPQ, 64, 32, c1b1, pidx,
                                                     pWt, 32, c1b2, pX, XLD, O1_OFS, 64);

    // ===== EdgeConv 2 (C=64, H=96, O=128) =====
    knn_k<64, 64><<<1024, 128>>>(pX, XLD, O1_OFS, pidx);
    prep_pq_k<<<(192 * 64 + 255) / 256, 256>>>(c2w1, pWt, 64, 96, 64);
    mmagemm_k<0, 0, 0><<<dim3(MT_P, 3), 256, SMEM>>>(pX + O1_OFS, XLD, 64, nullptr, 0, 0, nullptr, nullptr,
                                                     pWt, 64, nullptr, pPQ, 192, 0, 192);
    prep_wt_k<<<(128 * 96 + 255) / 256, 256>>>(c2w2, pWt, 96, 128, 96);
    mmagemm_k<1, 1, 1><<<dim3(MT_E, 2), 256, SMEM>>>(nullptr, 0, 96, pPQ, 192, 96, c2b1, pidx,
                                                     pWt, 96, c2b2, pX, XLD, O2_OFS, 128);

    // ===== EdgeConv 3 (C=128, H=192, O=256) =====
    knn_k<128, 128><<<1024, 128>>>(pX, XLD, O2_OFS, pidx);
    prep_pq_k<<<(384 * 128 + 255) / 256, 256>>>(c3w1, pWt, 128, 192, 128);
    mmagemm_k<0, 0, 0><<<dim3(MT_P, 6), 256, SMEM>>>(pX + O2_OFS, XLD, 128, nullptr, 0, 0, nullptr, nullptr,
                                                     pWt, 128, nullptr, pPQ, 384, 0, 384);
    prep_wt_k<<<(256 * 192 + 255) / 256, 256>>>(c3w2, pWt, 192, 256, 192);
    mmagemm_k<1, 1, 1><<<dim3(MT_E, 4), 256, SMEM>>>(nullptr, 0, 192, pPQ, 384, 192, c3b1, pidx,
                                                     pWt, 192, c3b2, pX, XLD, O3_OFS, 256);

    // ===== Head =====
    prep_head_k<<<(453 * 480 + 255) / 256, 256>>>(ow1, pWt, 453, 480);
    mmagemm_k<0, 1, 0><<<dim3(MT_P, 8), 256, SMEM>>>(pX, XLD, 456, nullptr, 0, 0, nullptr, nullptr,
                                                     pWt, 480, ob1, pH1, 456, 0, 453);
    prep_wt_k<<<(226 * 480 + 255) / 256, 256>>>(ow2, pWt, 453, 226, 480);
    mmagemm_k<0, 1, 0><<<dim3(MT_P, 4), 256, SMEM>>>(pH1, 456, 456, nullptr, 0, 0, nullptr, nullptr,
                                                     pWt, 480, ob2, pPQ, 228, 0, 226);
    head3_k<<<(NPTS * 32) / 256, 256>>>(pPQ, ow3, ob3, (float*)d_out);
}